// round 10
// baseline (speedup 1.0000x reference)
#include <cuda_runtime.h>
#include <cuda_fp16.h>
#include <math.h>

#define BB   64
#define PP   256
#define DV   1024
#define DT   768
#define SS   512
#define NSEG 32
#define PPT  8

#define MROWS 2048            // = BB*NSEG
#define TM    128             // GEMM M tile
#define TN    96              // GEMM N tile

// ---------------- scratch (static device globals; no allocation) ----------------
__device__ unsigned short g_Ah[MROWS * DV];   // fp16 hi split of segment means (K-major)
__device__ unsigned short g_Al[MROWS * DV];   // fp16 lo (residual) split
__device__ unsigned short g_Wh[DT * DV];      // fp16 W^T  [N=768][K=1024] single plane
__device__ float g_pooled[BB * DT];           // pooled (un-normalized) [64,768]
__device__ int   g_rank[BB * SS];             // placeholder rank or -1
__device__ int   g_phpos[BB * NSEG];          // position of r-th placeholder in row b
__device__ int   g_phcnt[BB];                 // per-row placeholder count
__device__ float g_sim[BB * BB];              // raw Gram matrix

// ---------------- PTX helpers (baseline PTX only: sm_80-class ops) --------------
__device__ __forceinline__ unsigned smem_u32(const void* p) {
    unsigned a;
    asm("{ .reg .u64 t; cvta.to.shared.u64 t, %1; cvt.u32.u64 %0, t; }" : "=r"(a) : "l"(p));
    return a;
}
__device__ __forceinline__ void cp16(unsigned saddr, const void* gptr) {
    asm volatile("cp.async.cg.shared.global [%0], [%1], 16;" :: "r"(saddr), "l"(gptr) : "memory");
}
__device__ __forceinline__ void cp_commit() {
    asm volatile("cp.async.commit_group;" ::: "memory");
}
__device__ __forceinline__ void cp_wait1() {
    asm volatile("cp.async.wait_group 1;" ::: "memory");
}
__device__ __forceinline__ void cp_wait0() {
    asm volatile("cp.async.wait_group 0;" ::: "memory");
}
__device__ __forceinline__ void ldsm4(unsigned* r, unsigned addr) {
    asm volatile("ldmatrix.sync.aligned.m8n8.x4.shared.b16 {%0,%1,%2,%3}, [%4];"
                 : "=r"(r[0]), "=r"(r[1]), "=r"(r[2]), "=r"(r[3]) : "r"(addr));
}
__device__ __forceinline__ void mma16816h(float* c, const unsigned* a, const unsigned* b) {
    asm volatile(
        "mma.sync.aligned.m16n8k16.row.col.f32.f16.f16.f32 "
        "{%0,%1,%2,%3}, {%4,%5,%6,%7}, {%8,%9}, {%0,%1,%2,%3};"
        : "+f"(c[0]), "+f"(c[1]), "+f"(c[2]), "+f"(c[3])
        : "r"(a[0]), "r"(a[1]), "r"(a[2]), "r"(a[3]), "r"(b[0]), "r"(b[1]));
}

// 2-way fp16 split (hi round-nearest, lo = fp16(residual)); a ~= hi+lo to 2^-22
__device__ __forceinline__ void split2h(float v, unsigned short& h, unsigned short& l) {
    __half hh = __float2half_rn(v);
    float r = v - __half2float(hh);
    __half hl = __float2half_rn(r);
    h = __half_as_ushort(hh);
    l = __half_as_ushort(hl);
}

// ---------------- K1: LayerNorm + segment mean -> fp16 splits -------------------
// R7 structure: all 8 patches in regs, one batched reduction pass, 2 syncs.
__global__ void k_ln_seg(const float* __restrict__ vis,
                         const float* __restrict__ gamma,
                         const float* __restrict__ beta) {
    int seg = blockIdx.x;
    int t = threadIdx.x;
    int lane = t & 31, w = t >> 5;

    __shared__ float rs[PPT][8], rq[PPT][8];
    __shared__ float s_mu[PPT], s_ri[PPT];

    const float* base = vis + (size_t)seg * PPT * DV;
    float4 x[PPT];
    float s[PPT], q[PPT];
    #pragma unroll
    for (int p = 0; p < PPT; p++) {
        x[p] = *(const float4*)(base + (size_t)p * DV + 4 * t);
        s[p] = x[p].x + x[p].y + x[p].z + x[p].w;
        q[p] = x[p].x * x[p].x + x[p].y * x[p].y + x[p].z * x[p].z + x[p].w * x[p].w;
    }
    #pragma unroll
    for (int p = 0; p < PPT; p++) {
        #pragma unroll
        for (int o = 16; o > 0; o >>= 1) {
            s[p] += __shfl_down_sync(0xffffffffu, s[p], o);
            q[p] += __shfl_down_sync(0xffffffffu, q[p], o);
        }
        if (lane == 0) { rs[p][w] = s[p]; rq[p][w] = q[p]; }
    }
    __syncthreads();
    if (t < PPT) {
        float ss = 0.f, qq = 0.f;
        #pragma unroll
        for (int i = 0; i < 8; i++) { ss += rs[t][i]; qq += rq[t][i]; }
        float mu = ss * (1.0f / DV);
        float var = qq * (1.0f / DV) - mu * mu;
        s_mu[t] = mu;
        s_ri[t] = rsqrtf(var + 1e-5f);
    }
    __syncthreads();

    float4 g4 = *(const float4*)(gamma + 4 * t);
    float4 b4 = *(const float4*)(beta + 4 * t);
    float a0 = 0.f, a1 = 0.f, a2 = 0.f, a3 = 0.f;
    #pragma unroll
    for (int p = 0; p < PPT; p++) {
        float mu = s_mu[p], ri = s_ri[p];
        a0 += (x[p].x - mu) * ri * g4.x + b4.x;
        a1 += (x[p].y - mu) * ri * g4.y + b4.y;
        a2 += (x[p].z - mu) * ri * g4.z + b4.z;
        a3 += (x[p].w - mu) * ri * g4.w + b4.w;
    }
    float v[4] = { a0 * (1.0f / PPT), a1 * (1.0f / PPT), a2 * (1.0f / PPT), a3 * (1.0f / PPT) };
    unsigned short h[4], l[4];
    #pragma unroll
    for (int i = 0; i < 4; i++) split2h(v[i], h[i], l[i]);
    size_t off = (size_t)seg * DV + 4 * t;
    uint2 ph = make_uint2((unsigned)h[0] | ((unsigned)h[1] << 16), (unsigned)h[2] | ((unsigned)h[3] << 16));
    uint2 pl = make_uint2((unsigned)l[0] | ((unsigned)l[1] << 16), (unsigned)l[2] | ((unsigned)l[3] << 16));
    *(uint2*)(g_Ah + off) = ph;
    *(uint2*)(g_Al + off) = pl;
}

// ---------------- K1b: transpose W [1024,768] -> W^T fp16 [768,1024] ------------
__global__ void k_wsplit(const float* __restrict__ Wp) {
    __shared__ float tile[32][33];
    int k0 = blockIdx.x * 32;       // K block
    int n0 = blockIdx.y * 32;       // N block
    int tx = threadIdx.x & 31, ty = threadIdx.x >> 5;   // 32x8
    #pragma unroll
    for (int i = 0; i < 4; i++)
        tile[ty + 8 * i][tx] = Wp[(size_t)(k0 + ty + 8 * i) * DT + n0 + tx];
    __syncthreads();
    #pragma unroll
    for (int i = 0; i < 4; i++) {
        int n = n0 + ty + 8 * i;
        int k = k0 + tx;
        g_Wh[(size_t)n * DV + k] = __half_as_ushort(__float2half_rn(tile[tx][ty + 8 * i]));
    }
}

// ---------------- K2: fp16 2-term split GEMM on mma.sync ------------------------
// C[2048,768] = (Ah+Al) @ Wh^T + bias (fp16 operands, fp32 accum).
// EXACT R7 pipeline: 128x96 tile, grid (16,8) one wave, 256 threads (4Mx2N warps),
// K chunks of 32, 2-stage double buffer, 2 __syncthreads per chunk.
// Epilogue scatters rows into out at placeholder slots + pooled mean.

#define KPAD 40
#define A_SPLIT_B (TM * KPAD * 2)      // 10240 B
#define B_SPLIT_B (TN * KPAD * 2)      // 7680 B
#define BUF_STRIDE (2 * A_SPLIT_B + B_SPLIT_B)   // 28160 B
#define GEMM_SMEM (2 * BUF_STRIDE)               // 56320 B

__device__ __forceinline__ void load_chunk(unsigned base, int tileM, int tileN, int c, int t) {
    #pragma unroll
    for (int s = 0; s < 2; s++) {
        const unsigned short* gA = s ? g_Al : g_Ah;
        #pragma unroll
        for (int i = 0; i < 2; i++) {
            int idx = t + 256 * i;              // 512 uint4 per split
            int row = idx >> 2, kq = idx & 3;
            cp16(base + s * A_SPLIT_B + row * (KPAD * 2) + kq * 16,
                 gA + (size_t)(tileM * TM + row) * DV + c * 32 + kq * 8);
        }
    }
    #pragma unroll
    for (int i = 0; i < 2; i++) {
        int idx = t + 256 * i;                  // 384 uint4
        if (idx < (TN * 32) / 8) {
            int row = idx >> 2, kq = idx & 3;
            cp16(base + 2 * A_SPLIT_B + row * (KPAD * 2) + kq * 16,
                 g_Wh + (size_t)(tileN * TN + row) * DV + c * 32 + kq * 8);
        }
    }
}

__global__ void __launch_bounds__(256, 1) k_gemm_tc(const float* __restrict__ bp,
                                                    float* __restrict__ out) {
    extern __shared__ __align__(16) unsigned char smem[];
    unsigned sb = smem_u32(smem);
    int t = threadIdx.x;
    int wid = t >> 5, lane = t & 31;
    int tileM = blockIdx.x, tileN = blockIdx.y;
    int warpM = (wid & 3) * 32, warpN = (wid >> 2) * 48;
    int g = lane >> 2, t4 = lane & 3;
    int l7 = lane & 7, mat = lane >> 3;

    int aRow = (mat & 1) * 8 + l7;
    int aK   = (mat >> 1) * 8;
    int bRow = (mat >> 1) * 8 + l7;
    int bK   = (mat & 1) * 8;

    float acc[2][6][4];
    #pragma unroll
    for (int i = 0; i < 2; i++)
        #pragma unroll
        for (int j = 0; j < 6; j++)
            #pragma unroll
            for (int k = 0; k < 4; k++) acc[i][j][k] = 0.f;

    load_chunk(sb, tileM, tileN, 0, t);
    cp_commit();

    for (int c = 0; c < DV / 32; c++) {
        if (c < DV / 32 - 1) {
            load_chunk(sb + ((c + 1) & 1) * BUF_STRIDE, tileM, tileN, c + 1, t);
            cp_commit();
            cp_wait1();
        } else {
            cp_wait0();
        }
        __syncthreads();

        unsigned base = sb + (c & 1) * BUF_STRIDE;
        #pragma unroll
        for (int kk = 0; kk < 2; kk++) {
            unsigned af[2][2][4];
            #pragma unroll
            for (int s = 0; s < 2; s++)
                #pragma unroll
                for (int mt = 0; mt < 2; mt++)
                    ldsm4(af[s][mt], base + s * A_SPLIT_B +
                          ((warpM + mt * 16 + aRow) * KPAD + kk * 16 + aK) * 2);
            unsigned bfr[6][2];
            #pragma unroll
            for (int nt = 0; nt < 3; nt++) {
                unsigned r[4];
                ldsm4(r, base + 2 * A_SPLIT_B +
                      ((warpN + nt * 16 + bRow) * KPAD + kk * 16 + bK) * 2);
                bfr[nt * 2][0] = r[0]; bfr[nt * 2][1] = r[1];
                bfr[nt * 2 + 1][0] = r[2]; bfr[nt * 2 + 1][1] = r[3];
            }
            #pragma unroll
            for (int s = 0; s < 2; s++)
                #pragma unroll
                for (int mt = 0; mt < 2; mt++)
                    #pragma unroll
                    for (int n = 0; n < 6; n++)
                        mma16816h(acc[mt][n], af[s][mt], bfr[n]);
        }
        __syncthreads();
    }

    // epilogue 1: scatter rows directly into out at their placeholder slots
    #pragma unroll
    for (int mt = 0; mt < 2; mt++) {
        #pragma unroll
        for (int half = 0; half < 2; half++) {
            int row = tileM * TM + warpM + mt * 16 + half * 8 + g;   // global segment row
            int b = row >> 5, r = row & 31;
            if (r < g_phcnt[b]) {
                int spos = g_phpos[b * NSEG + r];
                float* dst = out + ((size_t)b * SS + spos) * DT;
                #pragma unroll
                for (int n = 0; n < 6; n++) {
                    int col = tileN * TN + warpN + n * 8 + t4 * 2;
                    float2 v = make_float2(acc[mt][n][half * 2 + 0] + bp[col],
                                           acc[mt][n][half * 2 + 1] + bp[col + 1]);
                    *(float2*)(dst + col) = v;
                }
            }
        }
    }

    // epilogue 2: pooled = mean over this warp's 32 segment rows (= one batch b)
    #pragma unroll
    for (int n = 0; n < 6; n++) {
        float s0 = acc[0][n][0] + acc[0][n][2] + acc[1][n][0] + acc[1][n][2];
        float s1 = acc[0][n][1] + acc[0][n][3] + acc[1][n][1] + acc[1][n][3];
        #pragma unroll
        for (int o = 4; o < 32; o <<= 1) {
            s0 += __shfl_xor_sync(0xffffffffu, s0, o);
            s1 += __shfl_xor_sync(0xffffffffu, s1, o);
        }
        if (g == 0) {
            int b = tileM * 4 + (wid & 3);
            int col = tileN * TN + warpN + n * 8 + t4 * 2;
            g_pooled[b * DT + col]     = s0 * (1.0f / NSEG) + bp[col];
            g_pooled[b * DT + col + 1] = s1 * (1.0f / NSEG) + bp[col + 1];
        }
    }
}

// ---------------- K3a: placeholder rank + compacted positions -------------------
__global__ void k_rank(const int* __restrict__ ids, const int* __restrict__ php) {
    int b = blockIdx.x;
    int lane = threadIdx.x;
    int ph = *php;
    const int* row = ids + b * SS;
    int* orow = g_rank + b * SS;
    int base = 0;
    unsigned below = (1u << lane) - 1u;
    #pragma unroll
    for (int c = 0; c < SS / 32; c++) {
        int s = c * 32 + lane;
        int id = row[s];
        unsigned m = __ballot_sync(0xffffffffu, id == ph);
        int r = base + __popc(m & below);
        orow[s] = (id == ph) ? r : -1;
        if (id == ph && r < NSEG) g_phpos[b * NSEG + r] = s;
        base += __popc(m);
    }
    if (lane == 0) g_phcnt[b] = (base < NSEG) ? base : NSEG;
}

// ---------------- K3b: wte gather (all non-placeholder rows) --------------------
__global__ void k_emb_wte(const int* __restrict__ ids, const float* __restrict__ wte,
                          float* __restrict__ out) {
    int base = blockIdx.x * 8;
    int tid = threadIdx.x;         // 192 threads x float4 = 768 floats/row
    const float4* src[8];
    bool skip[8];
    #pragma unroll
    for (int r = 0; r < 8; r++) {
        int bs = base + r;
        int rk = g_rank[bs];
        skip[r] = (rk >= 0 && rk < NSEG);
        src[r] = (const float4*)(wte + (size_t)ids[bs] * DT);
    }
    float4 v[8];
    #pragma unroll
    for (int r = 0; r < 8; r++) if (!skip[r]) v[r] = src[r][tid];
    #pragma unroll
    for (int r = 0; r < 8; r++)
        if (!skip[r]) *(float4*)(out + (size_t)(base + r) * DT + 4 * tid) = v[r];
}

// ---------------- K4b: raw Gram matrix G = pooled @ pooled^T --------------------
__global__ void k_sim() {
    int i = blockIdx.x;
    int t = threadIdx.x;
    int w = t >> 5, lane = t & 31;
    const float* a = g_pooled + (size_t)i * DT;
    for (int j = w; j < BB; j += 8) {
        const float* bv = g_pooled + (size_t)j * DT;
        float d = 0.f;
        for (int k = lane; k < DT; k += 32) d += a[k] * bv[k];
        #pragma unroll
        for (int o = 16; o > 0; o >>= 1) d += __shfl_down_sync(0xffffffffu, d, o);
        if (lane == 0) g_sim[i * BB + j] = d;
    }
}

// ---------------- K4c: CE loss (normalize on the fly; symmetric) ----------------
__global__ void k_loss(float* __restrict__ out, int out_size) {
    int i = threadIdx.x;
    __shared__ float sh[2];
    float gii = g_sim[i * BB + i];
    float ri = rsqrtf(gii);
    float m = -1e30f;
    float sim[BB];
    for (int j = 0; j < BB; j++) {
        float gjj = g_sim[j * BB + j];
        float v = g_sim[i * BB + j] * ri * rsqrtf(gjj) * (1.0f / 0.07f);
        sim[j] = v;
        m = fmaxf(m, v);
    }
    float se = 0.f;
    for (int j = 0; j < BB; j++) se += expf(sim[j] - m);
    float lr = sim[i] - (m + logf(se));

    float v = lr;
    #pragma unroll
    for (int o = 16; o > 0; o >>= 1) v += __shfl_down_sync(0xffffffffu, v, o);
    int w = i >> 5;
    if ((i & 31) == 0) sh[w] = v;
    __syncthreads();
    if (i == 0) out[out_size - 1] = -(sh[0] + sh[1]) / (float)BB;
}

// ---------------- launch (fork/join; rank+wsplit+wte on side stream) ------------
extern "C" void kernel_launch(void* const* d_in, const int* in_sizes, int n_in,
                              void* d_out, int out_size) {
    const float* vis   = (const float*)d_in[0];
    const float* gamma = (const float*)d_in[1];
    const float* beta  = (const float*)d_in[2];
    const float* Wp    = (const float*)d_in[3];
    const float* bp    = (const float*)d_in[4];
    const float* wte   = (const float*)d_in[5];
    const int*   ids   = (const int*)d_in[6];
    const int*   php   = (const int*)d_in[7];
    float* out = (float*)d_out;

    static int inited = 0;
    static cudaStream_t s1;
    static cudaEvent_t e0, e_pre, e1;
    if (!inited) {
        cudaFuncSetAttribute(k_gemm_tc, cudaFuncAttributeMaxDynamicSharedMemorySize, GEMM_SMEM);
        cudaStreamCreateWithFlags(&s1, cudaStreamNonBlocking);
        cudaEventCreateWithFlags(&e0, cudaEventDisableTiming);
        cudaEventCreateWithFlags(&e_pre, cudaEventDisableTiming);
        cudaEventCreateWithFlags(&e1, cudaEventDisableTiming);
        inited = 1;
    }

    // fork side stream
    cudaEventRecord(e0, 0);
    cudaStreamWaitEvent(s1, e0, 0);

    // side branch: rank -> W transpose (both GEMM prerequisites) -> wte gather
    k_rank<<<BB, 32, 0, s1>>>(ids, php);
    k_wsplit<<<dim3(DV / 32, DT / 32), 256, 0, s1>>>(Wp);
    cudaEventRecord(e_pre, s1);
    k_emb_wte<<<(BB * SS) / 8, 192, 0, s1>>>(ids, wte, out);
    cudaEventRecord(e1, s1);

    // main branch: LN -> GEMM (scatters placeholder rows + pooled) -> sim -> loss
    k_ln_seg<<<BB * NSEG, 256>>>(vis, gamma, beta);
    cudaStreamWaitEvent(0, e_pre, 0);
    k_gemm_tc<<<dim3(MROWS / TM, DT / TN), 256, GEMM_SMEM>>>(bp, out);
    k_sim<<<BB, 256>>>();
    k_loss<<<1, 64>>>(out, out_size);

    // join
    cudaStreamWaitEvent(0, e1, 0);
}

// round 15
// speedup vs baseline: 1.0973x; 1.0973x over previous
#include <cuda_runtime.h>
#include <cuda_bf16.h>
#include <math.h>

#define BB   64
#define PP   256
#define DV   1024
#define DT   768
#define SS   512
#define NSEG 32
#define PPT  8

#define MROWS 2048            // = BB*NSEG
#define TM    128             // GEMM M tile
#define TN    96              // GEMM N tile

// ---------------- scratch (static device globals; no allocation) ----------------
__device__ unsigned short g_Ah[MROWS * DV];   // bf16 hi split of segment means (K-major)
__device__ unsigned short g_Am[MROWS * DV];   // bf16 mid split
__device__ unsigned short g_Wh[DT * DV];      // bf16 hi split of W^T  [N=768][K=1024]
__device__ unsigned short g_Wm[DT * DV];      // bf16 mid split
__device__ float g_pooled[BB * DT];           // pooled (un-normalized) [64,768]
__device__ int   g_rank[BB * SS];             // placeholder rank or -1
__device__ int   g_phpos[BB * NSEG];          // position of r-th placeholder in row b
__device__ int   g_phcnt[BB];                 // per-row placeholder count
__device__ float g_sim[BB * BB];              // raw Gram matrix

// ---------------- PTX helpers (baseline PTX only: sm_80-class ops) --------------
__device__ __forceinline__ unsigned smem_u32(const void* p) {
    unsigned a;
    asm("{ .reg .u64 t; cvta.to.shared.u64 t, %1; cvt.u32.u64 %0, t; }" : "=r"(a) : "l"(p));
    return a;
}
__device__ __forceinline__ void cp16(unsigned saddr, const void* gptr) {
    asm volatile("cp.async.cg.shared.global [%0], [%1], 16;" :: "r"(saddr), "l"(gptr) : "memory");
}
__device__ __forceinline__ void cp_commit() {
    asm volatile("cp.async.commit_group;" ::: "memory");
}
__device__ __forceinline__ void cp_wait1() {
    asm volatile("cp.async.wait_group 1;" ::: "memory");
}
__device__ __forceinline__ void cp_wait0() {
    asm volatile("cp.async.wait_group 0;" ::: "memory");
}
__device__ __forceinline__ void ldsm4(unsigned* r, unsigned addr) {
    asm volatile("ldmatrix.sync.aligned.m8n8.x4.shared.b16 {%0,%1,%2,%3}, [%4];"
                 : "=r"(r[0]), "=r"(r[1]), "=r"(r[2]), "=r"(r[3]) : "r"(addr));
}
__device__ __forceinline__ void mma16816(float* c, const unsigned* a, const unsigned* b) {
    asm volatile(
        "mma.sync.aligned.m16n8k16.row.col.f32.bf16.bf16.f32 "
        "{%0,%1,%2,%3}, {%4,%5,%6,%7}, {%8,%9}, {%0,%1,%2,%3};"
        : "+f"(c[0]), "+f"(c[1]), "+f"(c[2]), "+f"(c[3])
        : "r"(a[0]), "r"(a[1]), "r"(a[2]), "r"(a[3]), "r"(b[0]), "r"(b[1]));
}

// 2-way bf16 split (hi exact-rounded, mid = residual)
__device__ __forceinline__ void split2(float v, unsigned short& h, unsigned short& m) {
    __nv_bfloat16 bh = __float2bfloat16(v);
    float r1 = v - __bfloat162float(bh);
    __nv_bfloat16 bm = __float2bfloat16(r1);
    h = __bfloat16_as_ushort(bh);
    m = __bfloat16_as_ushort(bm);
}

// ---------------- K1: LayerNorm + segment mean -> bf16 splits -------------------
// TWO-PASS: pass 1 computes per-patch sums only (no x[] kept live -> ~32 regs,
// high occupancy); pass 2 reloads the same lines (L1/L2 hits) and normalizes.
__global__ void k_ln_seg(const float* __restrict__ vis,
                         const float* __restrict__ gamma,
                         const float* __restrict__ beta) {
    int seg = blockIdx.x;
    int t = threadIdx.x;
    int lane = t & 31, w = t >> 5;

    __shared__ float rs[PPT][8], rq[PPT][8];
    __shared__ float s_mu[PPT], s_ri[PPT];

    const float* base = vis + (size_t)seg * PPT * DV;

    // pass 1: stats
    float s[PPT], q[PPT];
    #pragma unroll
    for (int p = 0; p < PPT; p++) {
        float4 x = *(const float4*)(base + (size_t)p * DV + 4 * t);
        s[p] = x.x + x.y + x.z + x.w;
        q[p] = x.x * x.x + x.y * x.y + x.z * x.z + x.w * x.w;
    }
    #pragma unroll
    for (int p = 0; p < PPT; p++) {
        #pragma unroll
        for (int o = 16; o > 0; o >>= 1) {
            s[p] += __shfl_down_sync(0xffffffffu, s[p], o);
            q[p] += __shfl_down_sync(0xffffffffu, q[p], o);
        }
        if (lane == 0) { rs[p][w] = s[p]; rq[p][w] = q[p]; }
    }
    __syncthreads();
    if (t < PPT) {
        float ss = 0.f, qq = 0.f;
        #pragma unroll
        for (int i = 0; i < 8; i++) { ss += rs[t][i]; qq += rq[t][i]; }
        float mu = ss * (1.0f / DV);
        float var = qq * (1.0f / DV) - mu * mu;
        s_mu[t] = mu;
        s_ri[t] = rsqrtf(var + 1e-5f);
    }
    __syncthreads();

    // pass 2: reload (cache-resident) + normalize + accumulate segment mean
    float4 g4 = *(const float4*)(gamma + 4 * t);
    float4 b4 = *(const float4*)(beta + 4 * t);
    float a0 = 0.f, a1 = 0.f, a2 = 0.f, a3 = 0.f;
    #pragma unroll
    for (int p = 0; p < PPT; p++) {
        float4 x = *(const float4*)(base + (size_t)p * DV + 4 * t);
        float mu = s_mu[p], ri = s_ri[p];
        a0 += (x.x - mu) * ri * g4.x + b4.x;
        a1 += (x.y - mu) * ri * g4.y + b4.y;
        a2 += (x.z - mu) * ri * g4.z + b4.z;
        a3 += (x.w - mu) * ri * g4.w + b4.w;
    }
    float v[4] = { a0 * (1.0f / PPT), a1 * (1.0f / PPT), a2 * (1.0f / PPT), a3 * (1.0f / PPT) };
    unsigned short h[4], m[4];
    #pragma unroll
    for (int i = 0; i < 4; i++) split2(v[i], h[i], m[i]);
    size_t off = (size_t)seg * DV + 4 * t;
    uint2 ph = make_uint2((unsigned)h[0] | ((unsigned)h[1] << 16), (unsigned)h[2] | ((unsigned)h[3] << 16));
    uint2 pm = make_uint2((unsigned)m[0] | ((unsigned)m[1] << 16), (unsigned)m[2] | ((unsigned)m[3] << 16));
    *(uint2*)(g_Ah + off) = ph;
    *(uint2*)(g_Am + off) = pm;
}

// ---------------- K1b: transpose + split W [1024,768] -> W^T splits [768,1024] --
__global__ void k_wsplit(const float* __restrict__ Wp) {
    __shared__ float tile[32][33];
    int k0 = blockIdx.x * 32;       // K block
    int n0 = blockIdx.y * 32;       // N block
    int tx = threadIdx.x & 31, ty = threadIdx.x >> 5;   // 32x8
    #pragma unroll
    for (int i = 0; i < 4; i++)
        tile[ty + 8 * i][tx] = Wp[(size_t)(k0 + ty + 8 * i) * DT + n0 + tx];
    __syncthreads();
    #pragma unroll
    for (int i = 0; i < 4; i++) {
        int n = n0 + ty + 8 * i;
        int k = k0 + tx;
        float v = tile[tx][ty + 8 * i];
        unsigned short h, m;
        split2(v, h, m);
        size_t off = (size_t)n * DV + k;
        g_Wh[off] = h; g_Wm[off] = m;
    }
}

// ---------------- K2: bf16 split GEMM; epilogue scatters to out + pooled --------
// EXACT R7 GEMM (best measured config): 3 bf16 cross terms (hh, hm, mh),
// 128x96 tile, grid (16,8) one wave, 256 threads (4Mx2N warps), K chunks of 32,
// 2-stage cp.async double buffer.

#define KPAD 40
#define A_SPLIT_B (TM * KPAD * 2)      // 10240 B
#define B_SPLIT_B (TN * KPAD * 2)      // 7680 B
#define BUF_STRIDE (2 * A_SPLIT_B + 2 * B_SPLIT_B)   // 35840 B
#define GEMM_SMEM (2 * BUF_STRIDE)                   // 71680 B

__device__ __forceinline__ void load_chunk(unsigned base, int tileM, int tileN, int c, int t) {
    #pragma unroll
    for (int s = 0; s < 2; s++) {
        const unsigned short* gA = s ? g_Am : g_Ah;
        #pragma unroll
        for (int i = 0; i < 2; i++) {
            int idx = t + 256 * i;              // 512 uint4
            int row = idx >> 2, kq = idx & 3;
            cp16(base + s * A_SPLIT_B + row * (KPAD * 2) + kq * 16,
                 gA + (size_t)(tileM * TM + row) * DV + c * 32 + kq * 8);
        }
    }
    #pragma unroll
    for (int s = 0; s < 2; s++) {
        const unsigned short* gB = s ? g_Wm : g_Wh;
        #pragma unroll
        for (int i = 0; i < 2; i++) {
            int idx = t + 256 * i;              // 384 uint4
            if (idx < (TN * 32) / 8) {
                int row = idx >> 2, kq = idx & 3;
                cp16(base + 2 * A_SPLIT_B + s * B_SPLIT_B + row * (KPAD * 2) + kq * 16,
                     gB + (size_t)(tileN * TN + row) * DV + c * 32 + kq * 8);
            }
        }
    }
}

__global__ void __launch_bounds__(256, 1) k_gemm_tc(const float* __restrict__ bp,
                                                    float* __restrict__ out) {
    extern __shared__ __align__(16) unsigned char smem[];
    unsigned sb = smem_u32(smem);
    int t = threadIdx.x;
    int wid = t >> 5, lane = t & 31;
    int tileM = blockIdx.x, tileN = blockIdx.y;
    int warpM = (wid & 3) * 32, warpN = (wid >> 2) * 48;
    int g = lane >> 2, t4 = lane & 3;
    int l7 = lane & 7, mat = lane >> 3;

    int aRow = (mat & 1) * 8 + l7;
    int aK   = (mat >> 1) * 8;
    int bRow = (mat >> 1) * 8 + l7;
    int bK   = (mat & 1) * 8;

    float acc[2][6][4];
    #pragma unroll
    for (int i = 0; i < 2; i++)
        #pragma unroll
        for (int j = 0; j < 6; j++)
            #pragma unroll
            for (int k = 0; k < 4; k++) acc[i][j][k] = 0.f;

    load_chunk(sb, tileM, tileN, 0, t);
    cp_commit();

    for (int c = 0; c < DV / 32; c++) {
        if (c < DV / 32 - 1) {
            load_chunk(sb + ((c + 1) & 1) * BUF_STRIDE, tileM, tileN, c + 1, t);
            cp_commit();
            cp_wait1();
        } else {
            cp_wait0();
        }
        __syncthreads();

        unsigned base = sb + (c & 1) * BUF_STRIDE;
        #pragma unroll
        for (int kk = 0; kk < 2; kk++) {
            unsigned af[2][2][4];
            #pragma unroll
            for (int s = 0; s < 2; s++)
                #pragma unroll
                for (int mt = 0; mt < 2; mt++)
                    ldsm4(af[s][mt], base + s * A_SPLIT_B +
                          ((warpM + mt * 16 + aRow) * KPAD + kk * 16 + aK) * 2);
            unsigned bf[2][6][2];
            #pragma unroll
            for (int s = 0; s < 2; s++)
                #pragma unroll
                for (int nt = 0; nt < 3; nt++) {
                    unsigned r[4];
                    ldsm4(r, base + 2 * A_SPLIT_B + s * B_SPLIT_B +
                          ((warpN + nt * 16 + bRow) * KPAD + kk * 16 + bK) * 2);
                    bf[s][nt * 2][0] = r[0]; bf[s][nt * 2][1] = r[1];
                    bf[s][nt * 2 + 1][0] = r[2]; bf[s][nt * 2 + 1][1] = r[3];
                }
            #pragma unroll
            for (int tm = 0; tm < 3; tm++) {
                const int sa = (tm == 2) ? 1 : 0;
                const int sbv = (tm == 1) ? 1 : 0;
                #pragma unroll
                for (int mt = 0; mt < 2; mt++)
                    #pragma unroll
                    for (int n = 0; n < 6; n++)
                        mma16816(acc[mt][n], af[sa][mt], bf[sbv][n]);
            }
        }
        __syncthreads();
    }

    // epilogue 1: scatter rows directly into out at their placeholder slots
    #pragma unroll
    for (int mt = 0; mt < 2; mt++) {
        #pragma unroll
        for (int half = 0; half < 2; half++) {
            int row = tileM * TM + warpM + mt * 16 + half * 8 + g;   // global segment row
            int b = row >> 5, r = row & 31;
            if (r < g_phcnt[b]) {
                int spos = g_phpos[b * NSEG + r];
                float* dst = out + ((size_t)b * SS + spos) * DT;
                #pragma unroll
                for (int n = 0; n < 6; n++) {
                    int col = tileN * TN + warpN + n * 8 + t4 * 2;
                    float2 v = make_float2(acc[mt][n][half * 2 + 0] + bp[col],
                                           acc[mt][n][half * 2 + 1] + bp[col + 1]);
                    *(float2*)(dst + col) = v;
                }
            }
        }
    }

    // epilogue 2: pooled = mean over this warp's 32 segment rows (= one batch b)
    #pragma unroll
    for (int n = 0; n < 6; n++) {
        float s0 = acc[0][n][0] + acc[0][n][2] + acc[1][n][0] + acc[1][n][2];
        float s1 = acc[0][n][1] + acc[0][n][3] + acc[1][n][1] + acc[1][n][3];
        #pragma unroll
        for (int o = 4; o < 32; o <<= 1) {
            s0 += __shfl_xor_sync(0xffffffffu, s0, o);
            s1 += __shfl_xor_sync(0xffffffffu, s1, o);
        }
        if (g == 0) {
            int b = tileM * 4 + (wid & 3);
            int col = tileN * TN + warpN + n * 8 + t4 * 2;
            g_pooled[b * DT + col]     = s0 * (1.0f / NSEG) + bp[col];
            g_pooled[b * DT + col + 1] = s1 * (1.0f / NSEG) + bp[col + 1];
        }
    }
}

// ---------------- K3a: placeholder rank + compacted positions -------------------
__global__ void k_rank(const int* __restrict__ ids, const int* __restrict__ php) {
    int b = blockIdx.x;
    int lane = threadIdx.x;
    int ph = *php;
    const int* row = ids + b * SS;
    int* orow = g_rank + b * SS;
    int base = 0;
    unsigned below = (1u << lane) - 1u;
    #pragma unroll
    for (int c = 0; c < SS / 32; c++) {
        int s = c * 32 + lane;
        int id = row[s];
        unsigned m = __ballot_sync(0xffffffffu, id == ph);
        int r = base + __popc(m & below);
        orow[s] = (id == ph) ? r : -1;
        if (id == ph && r < NSEG) g_phpos[b * NSEG + r] = s;
        base += __popc(m);
    }
    if (lane == 0) g_phcnt[b] = (base < NSEG) ? base : NSEG;
}

// ---------------- K3b: wte gather (all non-placeholder rows) --------------------
__global__ void k_emb_wte(const int* __restrict__ ids, const float* __restrict__ wte,
                          float* __restrict__ out) {
    int base = blockIdx.x * 8;
    int tid = threadIdx.x;         // 192 threads x float4 = 768 floats/row
    const float4* src[8];
    bool skip[8];
    #pragma unroll
    for (int r = 0; r < 8; r++) {
        int bs = base + r;
        int rk = g_rank[bs];
        skip[r] = (rk >= 0 && rk < NSEG);
        src[r] = (const float4*)(wte + (size_t)ids[bs] * DT);
    }
    float4 v[8];
    #pragma unroll
    for (int r = 0; r < 8; r++) if (!skip[r]) v[r] = src[r][tid];
    #pragma unroll
    for (int r = 0; r < 8; r++)
        if (!skip[r]) *(float4*)(out + (size_t)(base + r) * DT + 4 * tid) = v[r];
}

// ---------------- K4b: raw Gram matrix G = pooled @ pooled^T --------------------
__global__ void k_sim() {
    int i = blockIdx.x;
    int t = threadIdx.x;
    int w = t >> 5, lane = t & 31;
    const float* a = g_pooled + (size_t)i * DT;
    for (int j = w; j < BB; j += 8) {
        const float* bv = g_pooled + (size_t)j * DT;
        float d = 0.f;
        for (int k = lane; k < DT; k += 32) d += a[k] * bv[k];
        #pragma unroll
        for (int o = 16; o > 0; o >>= 1) d += __shfl_down_sync(0xffffffffu, d, o);
        if (lane == 0) g_sim[i * BB + j] = d;
    }
}

// ---------------- K4c: CE loss (normalize on the fly; symmetric) ----------------
__global__ void k_loss(float* __restrict__ out, int out_size) {
    int i = threadIdx.x;
    __shared__ float sh[2];
    float gii = g_sim[i * BB + i];
    float ri = rsqrtf(gii);
    float m = -1e30f;
    float sim[BB];
    for (int j = 0; j < BB; j++) {
        float gjj = g_sim[j * BB + j];
        float v = g_sim[i * BB + j] * ri * rsqrtf(gjj) * (1.0f / 0.07f);
        sim[j] = v;
        m = fmaxf(m, v);
    }
    float se = 0.f;
    for (int j = 0; j < BB; j++) se += expf(sim[j] - m);
    float lr = sim[i] - (m + logf(se));

    float v = lr;
    #pragma unroll
    for (int o = 16; o > 0; o >>= 1) v += __shfl_down_sync(0xffffffffu, v, o);
    int w = i >> 5;
    if ((i & 31) == 0) sh[w] = v;
    __syncthreads();
    if (i == 0) out[out_size - 1] = -(sh[0] + sh[1]) / (float)BB;
}

// ---------------- launch (fork/join; rank+wsplit+wte on side stream) ------------
extern "C" void kernel_launch(void* const* d_in, const int* in_sizes, int n_in,
                              void* d_out, int out_size) {
    const float* vis   = (const float*)d_in[0];
    const float* gamma = (const float*)d_in[1];
    const float* beta  = (const float*)d_in[2];
    const float* Wp    = (const float*)d_in[3];
    const float* bp    = (const float*)d_in[4];
    const float* wte   = (const float*)d_in[5];
    const int*   ids   = (const int*)d_in[6];
    const int*   php   = (const int*)d_in[7];
    float* out = (float*)d_out;

    static int inited = 0;
    static cudaStream_t s1;
    static cudaEvent_t e0, e_pre, e1;
    if (!inited) {
        cudaFuncSetAttribute(k_gemm_tc, cudaFuncAttributeMaxDynamicSharedMemorySize, GEMM_SMEM);
        cudaStreamCreateWithFlags(&s1, cudaStreamNonBlocking);
        cudaEventCreateWithFlags(&e0, cudaEventDisableTiming);
        cudaEventCreateWithFlags(&e_pre, cudaEventDisableTiming);
        cudaEventCreateWithFlags(&e1, cudaEventDisableTiming);
        inited = 1;
    }

    // fork side stream
    cudaEventRecord(e0, 0);
    cudaStreamWaitEvent(s1, e0, 0);

    // side branch: rank -> W split (both GEMM prerequisites) -> wte gather
    k_rank<<<BB, 32, 0, s1>>>(ids, php);
    k_wsplit<<<dim3(DV / 32, DT / 32), 256, 0, s1>>>(Wp);
    cudaEventRecord(e_pre, s1);
    k_emb_wte<<<(BB * SS) / 8, 192, 0, s1>>>(ids, wte, out);
    cudaEventRecord(e1, s1);

    // main branch: LN -> GEMM (scatters placeholder rows + pooled) -> sim -> loss
    k_ln_seg<<<BB * NSEG, 256>>>(vis, gamma, beta);
    cudaStreamWaitEvent(0, e_pre, 0);
    k_gemm_tc<<<dim3(MROWS / TM, DT / TN), 256, GEMM_SMEM>>>(bp, out);
    k_sim<<<BB, 256>>>();
    k_loss<<<1, 64>>>(out, out_size);

    // join
    cudaStreamWaitEvent(0, e1, 0);
}